// round 13
// baseline (speedup 1.0000x reference)
#include <cuda_runtime.h>
#include <cuda_fp16.h>
#include <cstdint>

#define H    128
#define MAXE 1000000
#define MAXN 100000

// ---------------- device globals -------------------------------------------
__device__ int    d_cnt[6];    // accumulator (zeroed by bucket-tail each launch)
__device__ int    d_cnt2[6];   // snapshot used by k_decode
__device__ int    d_toff[7];
__device__ int    d_tick;      // bucket completion ticket (reset by last block)
__device__ int    d_perm6[6][MAXE];
__device__ __half d_x16[MAXN * H];
// frag-packed fp16 weights: [c][ks 0..31][nt2 0..7][lane 0..31] =
//   uint4{b0(nt even), b1(nt even), b0(nt odd), b1(nt odd)}
__device__ uint4  d_wb4[6 * 32 * 8 * 32];

__constant__ int c_lut[9] = {0, 1, 2, -1, 3, 4, -1, -1, 5};

// ---------------- helpers ----------------------------------------------------
__device__ __forceinline__ uint32_t smem_u32(const void* p) {
    uint32_t a;
    asm("{ .reg .u64 t; cvta.to.shared.u64 t, %1; cvt.u32.u64 %0, t; }" : "=r"(a) : "l"(p));
    return a;
}
__device__ __forceinline__ uint32_t h2bits(__half2 h) {
    return *reinterpret_cast<uint32_t*>(&h);
}
__device__ __forceinline__ void mma16816(float* d, const uint32_t* a,
                                         uint32_t b0, uint32_t b1) {
    asm volatile(
        "mma.sync.aligned.m16n8k16.row.col.f32.f16.f16.f32 "
        "{%0,%1,%2,%3}, {%4,%5,%6,%7}, {%8,%9}, {%0,%1,%2,%3};"
        : "+f"(d[0]), "+f"(d[1]), "+f"(d[2]), "+f"(d[3])
        : "r"(a[0]), "r"(a[1]), "r"(a[2]), "r"(a[3]), "r"(b0), "r"(b1));
}
__device__ __forceinline__ void ldsm4(uint32_t* r, uint32_t addr) {
    asm volatile("ldmatrix.sync.aligned.m8n8.x4.shared.b16 {%0,%1,%2,%3}, [%4];"
                 : "=r"(r[0]), "=r"(r[1]), "=r"(r[2]), "=r"(r[3]) : "r"(addr));
}
#define CP_ASYNC16(dst, src) \
    asm volatile("cp.async.cg.shared.global [%0], [%1], 16;" :: "r"(dst), "l"(src))
#define CP_COMMIT() asm volatile("cp.async.commit_group;" ::: "memory")
#define CP_WAIT0()  asm volatile("cp.async.wait_group 0;" ::: "memory")

__device__ __forceinline__ float4 ldcg4(const float* p) {
    float4 v;
    asm volatile("ld.global.cg.v4.f32 {%0,%1,%2,%3}, [%4];"
                 : "=f"(v.x), "=f"(v.y), "=f"(v.z), "=f"(v.w) : "l"(p));
    return v;
}

// ---------------- bucketing (4 edges / thread, fused prefix) -------------------
__global__ void k_bucket(const int* __restrict__ ei, const int* __restrict__ vol,
                         float* __restrict__ out, int E) {
    __shared__ int cnt[6], base[6], isLast;
    int i0 = (blockIdx.x * 256 + threadIdx.x) * 4;
    if (threadIdx.x < 6) cnt[threadIdx.x] = 0;
    __syncthreads();
    int c[4] = {-1, -1, -1, -1}, r[4];
    if (i0 + 3 < E) {
        int4 s = *reinterpret_cast<const int4*>(ei + i0);
        int4 d = *reinterpret_cast<const int4*>(ei + E + i0);
        int gs[4] = {vol[s.x] / 3, vol[s.y] / 3, vol[s.z] / 3, vol[s.w] / 3};
        int ge[4] = {vol[d.x] / 3, vol[d.y] / 3, vol[d.z] / 3, vol[d.w] / 3};
#pragma unroll
        for (int u = 0; u < 4; u++) {
            c[u] = c_lut[gs[u] * 3 + ge[u]];
            if (c[u] < 0) out[i0 + u] = 0.f;   // invalid edges only
        }
    } else {
        for (int u = 0; u < 4 && i0 + u < E; u++) {
            int i = i0 + u;
            c[u] = c_lut[(vol[ei[i]] / 3) * 3 + vol[ei[E + i]] / 3];
            if (c[u] < 0) out[i] = 0.f;
        }
    }
#pragma unroll
    for (int u = 0; u < 4; u++)
        if (c[u] >= 0) r[u] = atomicAdd(&cnt[c[u]], 1);
    __syncthreads();
    if (threadIdx.x < 6 && cnt[threadIdx.x] > 0)
        base[threadIdx.x] = atomicAdd(&d_cnt[threadIdx.x], cnt[threadIdx.x]);
    __syncthreads();
#pragma unroll
    for (int u = 0; u < 4; u++)
        if (c[u] >= 0) d_perm6[c[u]][base[c[u]] + r[u]] = i0 + u;

    // fused prefix: last block to finish computes tile offsets
    __threadfence();
    if (threadIdx.x == 0)
        isLast = (atomicAdd(&d_tick, 1) == (int)gridDim.x - 1);
    __syncthreads();
    if (isLast && threadIdx.x == 0) {
        int o = 0;
#pragma unroll
        for (int cc = 0; cc < 6; cc++) {
            int n = d_cnt[cc];
            d_cnt2[cc] = n;
            d_cnt[cc]  = 0;        // ready for next graph replay
            d_toff[cc] = o;
            o += (n + 127) >> 7;
        }
        d_toff[6] = o;
        d_tick = 0;                // ready for next graph replay
        __threadfence();
    }
}

// ---------------- x fp16 pre-convert (float4) ----------------------------------
__global__ void k_splitx(const float* __restrict__ x, int n4) {
    int i = blockIdx.x * 256 + threadIdx.x;
    if (i >= n4) return;
    float4 v = reinterpret_cast<const float4*>(x)[i];
    uint2 o;
    o.x = h2bits(__floats2half2_rn(v.x, v.y));
    o.y = h2bits(__floats2half2_rn(v.z, v.w));
    reinterpret_cast<uint2*>(d_x16)[i] = o;
}

// ---------------- weight transform (frag-packed fp16, uint4 coalesced) --------
__global__ void k_transW(const float* __restrict__ W1, const float* __restrict__ W2) {
    int idx = blockIdx.x * 256 + threadIdx.x;     // 49152 total
    if (idx >= 6 * 32 * 8 * 32) return;
    int lane = idx & 31;
    int nt2  = (idx >> 5) & 7;
    int ks   = (idx >> 8) & 31;
    int c    = idx >> 13;
    int gr = lane >> 2, tc = lane & 3;
    int k0 = ks * 16 + tc * 2;                    // global k (0..511)
    const float* Wsrc;
    int kk;
    if (ks < 24) { Wsrc = W1 + (size_t)c * 384 * 128; kk = k0; }
    else         { Wsrc = W2 + (size_t)c * 128 * 128; kk = k0 - 384; }
    uint32_t bw[4];
#pragma unroll
    for (int o = 0; o < 2; o++) {
        int n = (nt2 * 2 + o) * 8 + gr;
        float w00 = Wsrc[(size_t)kk * 128 + n];
        float w01 = Wsrc[(size_t)(kk + 1) * 128 + n];
        float w10 = Wsrc[(size_t)(kk + 8) * 128 + n];
        float w11 = Wsrc[(size_t)(kk + 9) * 128 + n];
        bw[o * 2]     = h2bits(__floats2half2_rn(w00, w01));
        bw[o * 2 + 1] = h2bits(__floats2half2_rn(w10, w11));
    }
    d_wb4[idx] = make_uint4(bw[0], bw[1], bw[2], bw[3]);
}

// ---------------- smem layout ---------------------------------------------------
#define BUF0     0         // 128 rows x 136 halves (272B stride) = 34816
#define BUF1     34816
#define OFF_PAR  69632     // 896 floats
#define OFF_OFFS 73216     // 384 ints
#define OFF_ROWI 74752     // 128 ints
#define OFF_REDS 75264     // 256 floats
#define OFF_REDQ 76288
#define OFF_DOTS 77312
#define SMEM_BYTES 78336
#define HROW 272           // bytes per staged row (136 halves)

// ---------------- fused decode ---------------------------------------------------
__global__ __launch_bounds__(256, 2) void k_decode(
    const float* __restrict__ e, const int* __restrict__ ei,
    const float* __restrict__ b1, const float* __restrict__ g1, const float* __restrict__ be1,
    const float* __restrict__ b2, const float* __restrict__ g2, const float* __restrict__ be2,
    const float* __restrict__ W3, const float* __restrict__ b3,
    float* __restrict__ out, int E) {
    extern __shared__ char smc[];

    // ---- flattened grid: block -> (combo, tile) ----
    const int b = blockIdx.x;
    if (b >= d_toff[6]) return;
    int c = 0;
#pragma unroll
    for (int q = 1; q < 6; q++) c += (b >= d_toff[q]);
    const int count = d_cnt2[c];
    const int m0    = (b - d_toff[c]) * 128;
    const int m     = min(128, count - m0);
    const int tid   = threadIdx.x;

    float* par  = (float*)(smc + OFF_PAR);
    int*   offs = (int*)(smc + OFF_OFFS);
    int*   rowi = (int*)(smc + OFF_ROWI);
    float* reds = (float*)(smc + OFF_REDS);
    float* redq = (float*)(smc + OFF_REDQ);
    float* dots = (float*)(smc + OFF_DOTS);

    if (tid < 128) {
        par[tid]       = b1[c * H + tid];
        par[128 + tid] = g1[c * H + tid];
        par[256 + tid] = be1[c * H + tid];
        par[384 + tid] = b2[c * H + tid];
        par[512 + tid] = g2[c * H + tid];
        par[640 + tid] = be2[c * H + tid];
        par[768 + tid] = W3[c * H + tid];
        int rr = (tid < m) ? tid : 0;
        int i  = d_perm6[c][m0 + rr];
        rowi[tid] = i;
        offs[tid]       = ei[i] * H;
        offs[128 + tid] = ei[E + i] * H;
        offs[256 + tid] = i * H;
    }
    __syncthreads();

    const int wid   = tid >> 5;
    const int lane  = tid & 31;
    const int gr    = lane >> 2;
    const int tc    = lane & 3;
    const int slab  = (wid & 3) * 32;
    const int nhalf = wid >> 2;
    const int rA0 = slab + gr, rB0 = rA0 + 8, rA1 = rA0 + 16, rB1 = rA0 + 24;

    // ldmatrix lane base addresses (16-row a-frag tiles), buffer-relative
    const uint32_t sb   = smem_u32(smc);
    const int      lrow = lane & 15;
    const int      lcol = lane >> 4;
    const uint32_t aBase = sb + (uint32_t)(slab + lrow) * HROW + lcol * 16;

    // x staging lane mapping (cp.async, 2 rows per warp per it)
    const int rr = wid * 2 + (lane >> 4);
    const int cb = (lane & 15) * 16;   // byte col within 256B row

    float acc[2][8][4];
#pragma unroll
    for (int mf = 0; mf < 2; mf++)
#pragma unroll
        for (int jt = 0; jt < 8; jt++)
#pragma unroll
            for (int u = 0; u < 4; u++) acc[mf][jt][u] = 0.f;

    // B pointer: [c][ks][nt2][lane] uint4; warp reads nt2 = nhalf*4 + jp
    const uint4* wbc = d_wb4 + (((size_t)c * 32) * 8 + nhalf * 4) * 32 + lane;

    // ---- prologue: cp.async seg0 x -> BUF0 ----
#pragma unroll
    for (int it = 0; it < 8; it++) {
        int r = it * 16 + rr;
        const char* src = (const char*)(d_x16 + offs[r]) + cb;
        CP_ASYNC16(sb + BUF0 + (uint32_t)r * HROW + cb, src);
    }
    CP_COMMIT();

    // ================= Layer 1 seg 0: xs, BUF0, B ksteps 0..7 ==================
    CP_WAIT0();
    __syncthreads();
    // prefetch seg1 x -> BUF1 (fully async, no regs held)
#pragma unroll
    for (int it = 0; it < 8; it++) {
        int r = it * 16 + rr;
        const char* src = (const char*)(d_x16 + offs[128 + r]) + cb;
        CP_ASYNC16(sb + BUF1 + (uint32_t)r * HROW + cb, src);
    }
    CP_COMMIT();
    {
        const uint32_t aH0 = aBase + BUF0;
        const uint32_t aH1 = aH0 + 16 * HROW;
#pragma unroll 4
        for (int ks8 = 0; ks8 < 8; ks8++) {
            uint32_t ah0[4], ah1[4];
            ldsm4(ah0, aH0 + ks8 * 32);
            ldsm4(ah1, aH1 + ks8 * 32);
            const uint4* bp = wbc + (size_t)ks8 * 256;
#pragma unroll
            for (int jp = 0; jp < 4; jp++) {
                uint4 bb = bp[jp * 32];
                mma16816(acc[0][jp * 2],     ah0, bb.x, bb.y);
                mma16816(acc[1][jp * 2],     ah1, bb.x, bb.y);
                mma16816(acc[0][jp * 2 + 1], ah0, bb.z, bb.w);
                mma16816(acc[1][jp * 2 + 1], ah1, bb.z, bb.w);
            }
        }
    }

    // ================= Layer 1 seg 1: xe, BUF1, B ksteps 8..15; e -> BUF0 ======
    CP_WAIT0();
    __syncthreads();
    {
        const uint32_t aH0 = aBase + BUF1;
        const uint32_t aH1 = aH0 + 16 * HROW;
        float4 ev[2];
        int    er[2];
#pragma unroll 2
        for (int ks8 = 0; ks8 < 8; ks8++) {
            // store e batch (loaded one kstep earlier), prefetch next batch
            if (ks8 > 0) {
#pragma unroll
                for (int u = 0; u < 2; u++) {
                    uint32_t h0 = h2bits(__floats2half2_rn(ev[u].x, ev[u].y));
                    uint32_t h1 = h2bits(__floats2half2_rn(ev[u].z, ev[u].w));
                    *(uint2*)(smc + BUF0 + er[u] * HROW + lane * 8) =
                        make_uint2(h0, h1);
                }
            }
#pragma unroll
            for (int u = 0; u < 2; u++) {
                int r = (ks8 * 2 + u) * 8 + wid;
                er[u] = r;
                ev[u] = ldcg4(e + offs[256 + r] + lane * 4);
            }
            uint32_t ah0[4], ah1[4];
            ldsm4(ah0, aH0 + ks8 * 32);
            ldsm4(ah1, aH1 + ks8 * 32);
            const uint4* bp = wbc + (size_t)(8 + ks8) * 256;
#pragma unroll
            for (int jp = 0; jp < 4; jp++) {
                uint4 bb = bp[jp * 32];
                mma16816(acc[0][jp * 2],     ah0, bb.x, bb.y);
                mma16816(acc[1][jp * 2],     ah1, bb.x, bb.y);
                mma16816(acc[0][jp * 2 + 1], ah0, bb.z, bb.w);
                mma16816(acc[1][jp * 2 + 1], ah1, bb.z, bb.w);
            }
        }
        // flush last e batch
#pragma unroll
        for (int u = 0; u < 2; u++) {
            uint32_t h0 = h2bits(__floats2half2_rn(ev[u].x, ev[u].y));
            uint32_t h1 = h2bits(__floats2half2_rn(ev[u].z, ev[u].w));
            *(uint2*)(smc + BUF0 + er[u] * HROW + lane * 8) = make_uint2(h0, h1);
        }
    }

    // ================= Layer 1 seg 2: e, BUF0, B ksteps 16..23 =================
    __syncthreads();   // e stores visible; BUF1 reads done
    {
        const uint32_t aH0 = aBase + BUF0;
        const uint32_t aH1 = aH0 + 16 * HROW;
#pragma unroll 4
        for (int ks8 = 0; ks8 < 8; ks8++) {
            uint32_t ah0[4], ah1[4];
            ldsm4(ah0, aH0 + ks8 * 32);
            ldsm4(ah1, aH1 + ks8 * 32);
            const uint4* bp = wbc + (size_t)(16 + ks8) * 256;
#pragma unroll
            for (int jp = 0; jp < 4; jp++) {
                uint4 bb = bp[jp * 32];
                mma16816(acc[0][jp * 2],     ah0, bb.x, bb.y);
                mma16816(acc[1][jp * 2],     ah1, bb.x, bb.y);
                mma16816(acc[0][jp * 2 + 1], ah0, bb.z, bb.w);
                mma16816(acc[1][jp * 2 + 1], ah1, bb.z, bb.w);
            }
        }
    }

    // ---------------- epilogue 1: bias + LN + ReLU -> h in BUF1 ----------------
    __syncthreads();
    {
        float sA[2] = {0, 0}, qA[2] = {0, 0}, sB[2] = {0, 0}, qB[2] = {0, 0};
#pragma unroll
        for (int mf = 0; mf < 2; mf++)
#pragma unroll
            for (int jt = 0; jt < 8; jt++) {
                int col = nhalf * 64 + jt * 8 + tc * 2;
                float2 bb = *(const float2*)(par + col);
                float v0 = acc[mf][jt][0] + bb.x, v1 = acc[mf][jt][1] + bb.y;
                float v2 = acc[mf][jt][2] + bb.x, v3 = acc[mf][jt][3] + bb.y;
                acc[mf][jt][0] = v0; acc[mf][jt][1] = v1;
                acc[mf][jt][2] = v2; acc[mf][jt][3] = v3;
                sA[mf] += v0 + v1; qA[mf] += v0 * v0 + v1 * v1;
                sB[mf] += v2 + v3; qB[mf] += v2 * v2 + v3 * v3;
            }
#pragma unroll
        for (int d = 1; d < 4; d <<= 1) {
            sA[0] += __shfl_xor_sync(~0u, sA[0], d); qA[0] += __shfl_xor_sync(~0u, qA[0], d);
            sB[0] += __shfl_xor_sync(~0u, sB[0], d); qB[0] += __shfl_xor_sync(~0u, qB[0], d);
            sA[1] += __shfl_xor_sync(~0u, sA[1], d); qA[1] += __shfl_xor_sync(~0u, qA[1], d);
            sB[1] += __shfl_xor_sync(~0u, sB[1], d); qB[1] += __shfl_xor_sync(~0u, qB[1], d);
        }
        if (tc == 0) {
            reds[rA0 * 2 + nhalf] = sA[0]; redq[rA0 * 2 + nhalf] = qA[0];
            reds[rB0 * 2 + nhalf] = sB[0]; redq[rB0 * 2 + nhalf] = qB[0];
            reds[rA1 * 2 + nhalf] = sA[1]; redq[rA1 * 2 + nhalf] = qA[1];
            reds[rB1 * 2 + nhalf] = sB[1]; redq[rB1 * 2 + nhalf] = qB[1];
        }
        __syncthreads();
        int   rw[4] = {rA0, rB0, rA1, rB1};
        float mu[4], iv[4];
#pragma unroll
        for (int u = 0; u < 4; u++) {
            float st = reds[rw[u] * 2] + reds[rw[u] * 2 + 1];
            float qt = redq[rw[u] * 2] + redq[rw[u] * 2 + 1];
            mu[u] = st * (1.f / 128.f);
            iv[u] = rsqrtf(qt * (1.f / 128.f) - mu[u] * mu[u] + 1e-5f);
        }
#pragma unroll
        for (int mf = 0; mf < 2; mf++)
#pragma unroll
            for (int jt = 0; jt < 8; jt++) {
                int col = nhalf * 64 + jt * 8 + tc * 2;
                float2 gg = *(const float2*)(par + 128 + col);
                float2 ee = *(const float2*)(par + 256 + col);
                int ua = mf * 2, ub = mf * 2 + 1;
                float h0 = fmaxf((acc[mf][jt][0] - mu[ua]) * iv[ua] * gg.x + ee.x, 0.f);
                float h1 = fmaxf((acc[mf][jt][1] - mu[ua]) * iv[ua] * gg.y + ee.y, 0.f);
                float h2 = fmaxf((acc[mf][jt][2] - mu[ub]) * iv[ub] * gg.x + ee.x, 0.f);
                float h3 = fmaxf((acc[mf][jt][3] - mu[ub]) * iv[ub] * gg.y + ee.y, 0.f);
                *(uint32_t*)(smc + BUF1 + rw[ua] * HROW + col * 2) =
                    h2bits(__floats2half2_rn(h0, h1));
                *(uint32_t*)(smc + BUF1 + rw[ub] * HROW + col * 2) =
                    h2bits(__floats2half2_rn(h2, h3));
            }
    }
    __syncthreads();

    // ================= Layer 2: K = 128, A = h in BUF1 =========================
#pragma unroll
    for (int mf = 0; mf < 2; mf++)
#pragma unroll
        for (int jt = 0; jt < 8; jt++)
#pragma unroll
            for (int u = 0; u < 4; u++) acc[mf][jt][u] = 0.f;

    {
        const uint32_t aH0 = aBase + BUF1;
        const uint32_t aH1 = aH0 + 16 * HROW;
#pragma unroll 4
        for (int ks8 = 0; ks8 < 8; ks8++) {
            uint32_t ah0[4], ah1[4];
            ldsm4(ah0, aH0 + ks8 * 32);
            ldsm4(ah1, aH1 + ks8 * 32);
            const uint4* bp = wbc + (size_t)(24 + ks8) * 256;
#pragma unroll
            for (int jp = 0; jp < 4; jp++) {
                uint4 bb = bp[jp * 32];
                mma16816(acc[0][jp * 2],     ah0, bb.x, bb.y);
                mma16816(acc[1][jp * 2],     ah1, bb.x, bb.y);
                mma16816(acc[0][jp * 2 + 1], ah0, bb.z, bb.w);
                mma16816(acc[1][jp * 2 + 1], ah1, bb.z, bb.w);
            }
        }
    }

    // ---------------- epilogue 2: bias + LN + ReLU + layer-3 dot ---------------
    {
        float sA[2] = {0, 0}, qA[2] = {0, 0}, sB[2] = {0, 0}, qB[2] = {0, 0};
#pragma unroll
        for (int mf = 0; mf < 2; mf++)
#pragma unroll
            for (int jt = 0; jt < 8; jt++) {
                int col = nhalf * 64 + jt * 8 + tc * 2;
                float2 bb = *(const float2*)(par + 384 + col);
                float v0 = acc[mf][jt][0] + bb.x, v1 = acc[mf][jt][1] + bb.y;
                float v2 = acc[mf][jt][2] + bb.x, v3 = acc[mf][jt][3] + bb.y;
                acc[mf][jt][0] = v0; acc[mf][jt][1] = v1;
                acc[mf][jt][2] = v2; acc[mf][jt][3] = v3;
                sA[mf] += v0 + v1; qA[mf] += v0 * v0 + v1 * v1;
                sB[mf] += v2 + v3; qB[mf] += v2 * v2 + v3 * v3;
            }
#pragma unroll
        for (int d = 1; d < 4; d <<= 1) {
            sA[0] += __shfl_xor_sync(~0u, sA[0], d); qA[0] += __shfl_xor_sync(~0u, qA[0], d);
            sB[0] += __shfl_xor_sync(~0u, sB[0], d); qB[0] += __shfl_xor_sync(~0u, qB[0], d);
            sA[1] += __shfl_xor_sync(~0u, sA[1], d); qA[1] += __shfl_xor_sync(~0u, qA[1], d);
            sB[1] += __shfl_xor_sync(~0u, sB[1], d); qB[1] += __shfl_xor_sync(~0u, qB[1], d);
        }
        __syncthreads();   // protect reds/redq reuse
        if (tc == 0) {
            reds[rA0 * 2 + nhalf] = sA[0]; redq[rA0 * 2 + nhalf] = qA[0];
            reds[rB0 * 2 + nhalf] = sB[0]; redq[rB0 * 2 + nhalf] = qB[0];
            reds[rA1 * 2 + nhalf] = sA[1]; redq[rA1 * 2 + nhalf] = qA[1];
            reds[rB1 * 2 + nhalf] = sB[1]; redq[rB1 * 2 + nhalf] = qB[1];
        }
        __syncthreads();
        int   rw[4] = {rA0, rB0, rA1, rB1};
        float mu[4], iv[4], dt[4] = {0, 0, 0, 0};
#pragma unroll
        for (int u = 0; u < 4; u++) {
            float st = reds[rw[u] * 2] + reds[rw[u] * 2 + 1];
            float qt = redq[rw[u] * 2] + redq[rw[u] * 2 + 1];
            mu[u] = st * (1.f / 128.f);
            iv[u] = rsqrtf(qt * (1.f / 128.f) - mu[u] * mu[u] + 1e-5f);
        }
#pragma unroll
        for (int mf = 0; mf < 2; mf++)
#pragma unroll
            for (int jt = 0; jt < 8; jt++) {
                int col = nhalf * 64 + jt * 8 + tc * 2;
                float2 gg = *(const float2*)(par + 512 + col);
                float2 ee = *(const float2*)(par + 640 + col);
                float2 ww = *(const float2*)(par + 768 + col);
                int ua = mf * 2, ub = mf * 2 + 1;
                float h0 = fmaxf((acc[mf][jt][0] - mu[ua]) * iv[ua] * gg.x + ee.x, 0.f);
                float h1 = fmaxf((acc[mf][jt][1] - mu[ua]) * iv[ua] * gg.y + ee.y, 0.f);
                float h2 = fmaxf((acc[mf][jt][2] - mu[ub]) * iv[ub] * gg.x + ee.x, 0.f);
                float h3 = fmaxf((acc[mf][jt][3] - mu[ub]) * iv[ub] * gg.y + ee.y, 0.f);
                dt[ua] += h0 * ww.x + h1 * ww.y;
                dt[ub] += h2 * ww.x + h3 * ww.y;
            }
#pragma unroll
        for (int d = 1; d < 4; d <<= 1) {
            dt[0] += __shfl_xor_sync(~0u, dt[0], d);
            dt[1] += __shfl_xor_sync(~0u, dt[1], d);
            dt[2] += __shfl_xor_sync(~0u, dt[2], d);
            dt[3] += __shfl_xor_sync(~0u, dt[3], d);
        }
        if (tc == 0) {
#pragma unroll
            for (int u = 0; u < 4; u++) dots[rw[u] * 2 + nhalf] = dt[u];
        }
        __syncthreads();
        if (tid < m)
            out[rowi[tid]] = dots[tid * 2] + dots[tid * 2 + 1] + b3[c];
    }
}

// ---------------- launch ----------------------------------------------------------
extern "C" void kernel_launch(void* const* d_in, const int* in_sizes, int n_in,
                              void* d_out, int out_size) {
    const float* x   = (const float*)d_in[0];
    const int*   ei  = (const int*)d_in[1];
    const float* e   = (const float*)d_in[2];
    const int*   vol = (const int*)d_in[3];
    const float* W1  = (const float*)d_in[4];
    const float* b1  = (const float*)d_in[5];
    const float* g1  = (const float*)d_in[6];
    const float* be1 = (const float*)d_in[7];
    const float* W2  = (const float*)d_in[8];
    const float* b2  = (const float*)d_in[9];
    const float* g2  = (const float*)d_in[10];
    const float* be2 = (const float*)d_in[11];
    const float* W3  = (const float*)d_in[12];
    const float* b3  = (const float*)d_in[13];
    float* out = (float*)d_out;

    int E = in_sizes[1] / 2;
    if (E > MAXE) E = MAXE;
    int N = in_sizes[0] / H;
    if (N > MAXN) N = MAXN;

    cudaFuncSetAttribute(k_decode, cudaFuncAttributeMaxDynamicSharedMemorySize, SMEM_BYTES);

    // capture-forked side streams for independent prep work (created once;
    // host-side resources only — no device allocations)
    static cudaStream_t s1 = nullptr, s2 = nullptr;
    static cudaEvent_t  evFork = nullptr, evJ1 = nullptr, evJ2 = nullptr;
    if (!s1) {
        cudaStreamCreateWithFlags(&s1, cudaStreamNonBlocking);
        cudaStreamCreateWithFlags(&s2, cudaStreamNonBlocking);
        cudaEventCreateWithFlags(&evFork, cudaEventDisableTiming);
        cudaEventCreateWithFlags(&evJ1, cudaEventDisableTiming);
        cudaEventCreateWithFlags(&evJ2, cudaEventDisableTiming);
    }

    // fork
    cudaEventRecord(evFork, 0);
    cudaStreamWaitEvent(s1, evFork, 0);
    cudaStreamWaitEvent(s2, evFork, 0);

    // s1: x fp16 convert   s2: weight transform   s0: bucketing (fused prefix)
    int n4 = N * (H / 4);
    k_splitx<<<(n4 + 255) / 256, 256, 0, s1>>>(x, n4);
    k_transW<<<(6 * 32 * 8 * 32 + 255) / 256, 256, 0, s2>>>(W1, W2);
    int nth = (E + 3) / 4;
    k_bucket<<<(nth + 255) / 256, 256>>>(ei, vol, out, E);

    // join
    cudaEventRecord(evJ1, s1);
    cudaEventRecord(evJ2, s2);
    cudaStreamWaitEvent(0, evJ1, 0);
    cudaStreamWaitEvent(0, evJ2, 0);

    int gx = (E + 127) / 128 + 6;
    k_decode<<<gx, 256, SMEM_BYTES>>>(e, ei, b1, g1, be1, b2, g2, be2,
                                      W3, b3, out, E);
}

// round 14
// speedup vs baseline: 1.0419x; 1.0419x over previous
#include <cuda_runtime.h>
#include <cuda_fp16.h>
#include <cstdint>

#define H    128
#define MAXE 1000000
#define MAXN 100000

// ---------------- device globals -------------------------------------------
__device__ int    d_cnt[6];    // accumulator (zeroed by bucket-tail each launch)
__device__ int    d_cnt2[6];   // snapshot used by k_decode
__device__ int    d_toff[7];
__device__ int    d_tick;      // bucket completion ticket (reset by last block)
__device__ int    d_perm6[6][MAXE];
__device__ __half d_x16[MAXN * H];
// frag-packed fp16 weights: [c][ks 0..31][nt2 0..7][lane 0..31] =
//   uint4{b0(nt even), b1(nt even), b0(nt odd), b1(nt odd)}
__device__ uint4  d_wb4[6 * 32 * 8 * 32];

__constant__ int c_lut[9] = {0, 1, 2, -1, 3, 4, -1, -1, 5};

// ---------------- helpers ----------------------------------------------------
__device__ __forceinline__ uint32_t smem_u32(const void* p) {
    uint32_t a;
    asm("{ .reg .u64 t; cvta.to.shared.u64 t, %1; cvt.u32.u64 %0, t; }" : "=r"(a) : "l"(p));
    return a;
}
__device__ __forceinline__ uint32_t h2bits(__half2 h) {
    return *reinterpret_cast<uint32_t*>(&h);
}
__device__ __forceinline__ void mma16816(float* d, const uint32_t* a,
                                         uint32_t b0, uint32_t b1) {
    asm volatile(
        "mma.sync.aligned.m16n8k16.row.col.f32.f16.f16.f32 "
        "{%0,%1,%2,%3}, {%4,%5,%6,%7}, {%8,%9}, {%0,%1,%2,%3};"
        : "+f"(d[0]), "+f"(d[1]), "+f"(d[2]), "+f"(d[3])
        : "r"(a[0]), "r"(a[1]), "r"(a[2]), "r"(a[3]), "r"(b0), "r"(b1));
}
__device__ __forceinline__ void ldsm4(uint32_t* r, uint32_t addr) {
    asm volatile("ldmatrix.sync.aligned.m8n8.x4.shared.b16 {%0,%1,%2,%3}, [%4];"
                 : "=r"(r[0]), "=r"(r[1]), "=r"(r[2]), "=r"(r[3]) : "r"(addr));
}
#define CP_ASYNC16(dst, src) \
    asm volatile("cp.async.cg.shared.global [%0], [%1], 16;" :: "r"(dst), "l"(src))
#define CP_COMMIT() asm volatile("cp.async.commit_group;" ::: "memory")
#define CP_WAIT0()  asm volatile("cp.async.wait_group 0;" ::: "memory")

__device__ __forceinline__ float4 ldcg4(const float* p) {
    float4 v;
    asm volatile("ld.global.cg.v4.f32 {%0,%1,%2,%3}, [%4];"
                 : "=f"(v.x), "=f"(v.y), "=f"(v.z), "=f"(v.w) : "l"(p));
    return v;
}

// ---------------- bucketing (4 edges / thread, fused prefix) -------------------
__global__ void k_bucket(const int* __restrict__ ei, const int* __restrict__ vol,
                         float* __restrict__ out, int E) {
    __shared__ int cnt[6], base[6], isLast;
    int i0 = (blockIdx.x * 256 + threadIdx.x) * 4;
    if (threadIdx.x < 6) cnt[threadIdx.x] = 0;
    __syncthreads();
    int c[4] = {-1, -1, -1, -1}, r[4];
    if (i0 + 3 < E) {
        int4 s = *reinterpret_cast<const int4*>(ei + i0);
        int4 d = *reinterpret_cast<const int4*>(ei + E + i0);
        int gs[4] = {vol[s.x] / 3, vol[s.y] / 3, vol[s.z] / 3, vol[s.w] / 3};
        int ge[4] = {vol[d.x] / 3, vol[d.y] / 3, vol[d.z] / 3, vol[d.w] / 3};
#pragma unroll
        for (int u = 0; u < 4; u++) {
            c[u] = c_lut[gs[u] * 3 + ge[u]];
            if (c[u] < 0) out[i0 + u] = 0.f;   // invalid edges only
        }
    } else {
        for (int u = 0; u < 4 && i0 + u < E; u++) {
            int i = i0 + u;
            c[u] = c_lut[(vol[ei[i]] / 3) * 3 + vol[ei[E + i]] / 3];
            if (c[u] < 0) out[i] = 0.f;
        }
    }
#pragma unroll
    for (int u = 0; u < 4; u++)
        if (c[u] >= 0) r[u] = atomicAdd(&cnt[c[u]], 1);
    __syncthreads();
    if (threadIdx.x < 6 && cnt[threadIdx.x] > 0)
        base[threadIdx.x] = atomicAdd(&d_cnt[threadIdx.x], cnt[threadIdx.x]);
    __syncthreads();
#pragma unroll
    for (int u = 0; u < 4; u++)
        if (c[u] >= 0) d_perm6[c[u]][base[c[u]] + r[u]] = i0 + u;

    // fused prefix: last block to finish computes tile offsets
    __threadfence();
    if (threadIdx.x == 0)
        isLast = (atomicAdd(&d_tick, 1) == (int)gridDim.x - 1);
    __syncthreads();
    if (isLast && threadIdx.x == 0) {
        int o = 0;
#pragma unroll
        for (int cc = 0; cc < 6; cc++) {
            int n = d_cnt[cc];
            d_cnt2[cc] = n;
            d_cnt[cc]  = 0;        // ready for next graph replay
            d_toff[cc] = o;
            o += (n + 127) >> 7;
        }
        d_toff[6] = o;
        d_tick = 0;                // ready for next graph replay
        __threadfence();
    }
}

// ---------------- x fp16 pre-convert (float4) ----------------------------------
__global__ void k_splitx(const float* __restrict__ x, int n4) {
    int i = blockIdx.x * 256 + threadIdx.x;
    if (i >= n4) return;
    float4 v = reinterpret_cast<const float4*>(x)[i];
    uint2 o;
    o.x = h2bits(__floats2half2_rn(v.x, v.y));
    o.y = h2bits(__floats2half2_rn(v.z, v.w));
    reinterpret_cast<uint2*>(d_x16)[i] = o;
}

// ---------------- weight transform (frag-packed fp16, uint4 coalesced) --------
__global__ void k_transW(const float* __restrict__ W1, const float* __restrict__ W2) {
    int idx = blockIdx.x * 256 + threadIdx.x;     // 49152 total
    if (idx >= 6 * 32 * 8 * 32) return;
    int lane = idx & 31;
    int nt2  = (idx >> 5) & 7;
    int ks   = (idx >> 8) & 31;
    int c    = idx >> 13;
    int gr = lane >> 2, tc = lane & 3;
    int k0 = ks * 16 + tc * 2;                    // global k (0..511)
    const float* Wsrc;
    int kk;
    if (ks < 24) { Wsrc = W1 + (size_t)c * 384 * 128; kk = k0; }
    else         { Wsrc = W2 + (size_t)c * 128 * 128; kk = k0 - 384; }
    uint32_t bw[4];
#pragma unroll
    for (int o = 0; o < 2; o++) {
        int n = (nt2 * 2 + o) * 8 + gr;
        float w00 = Wsrc[(size_t)kk * 128 + n];
        float w01 = Wsrc[(size_t)(kk + 1) * 128 + n];
        float w10 = Wsrc[(size_t)(kk + 8) * 128 + n];
        float w11 = Wsrc[(size_t)(kk + 9) * 128 + n];
        bw[o * 2]     = h2bits(__floats2half2_rn(w00, w01));
        bw[o * 2 + 1] = h2bits(__floats2half2_rn(w10, w11));
    }
    d_wb4[idx] = make_uint4(bw[0], bw[1], bw[2], bw[3]);
}

// ---------------- smem layout ---------------------------------------------------
#define BUF0     0         // 128 rows x 136 halves (272B stride) = 34816
#define BUF1     34816
#define OFF_PAR  69632     // 896 floats
#define OFF_OFFS 73216     // 384 ints
#define OFF_ROWI 74752     // 128 ints
#define OFF_REDS 75264     // 256 floats
#define OFF_REDQ 76288
#define OFF_DOTS 77312
#define SMEM_BYTES 78336
#define HROW 272           // bytes per staged row (136 halves)

// ---------------- fused decode ---------------------------------------------------
__global__ __launch_bounds__(256, 2) void k_decode(
    const float* __restrict__ e, const int* __restrict__ ei,
    const float* __restrict__ b1, const float* __restrict__ g1, const float* __restrict__ be1,
    const float* __restrict__ b2, const float* __restrict__ g2, const float* __restrict__ be2,
    const float* __restrict__ W3, const float* __restrict__ b3,
    float* __restrict__ out, int E) {
    extern __shared__ char smc[];

    // ---- flattened grid: block -> (combo, tile) ----
    const int b = blockIdx.x;
    if (b >= d_toff[6]) return;
    int c = 0;
#pragma unroll
    for (int q = 1; q < 6; q++) c += (b >= d_toff[q]);
    const int count = d_cnt2[c];
    const int m0    = (b - d_toff[c]) * 128;
    const int m     = min(128, count - m0);
    const int tid   = threadIdx.x;

    float* par  = (float*)(smc + OFF_PAR);
    int*   offs = (int*)(smc + OFF_OFFS);
    int*   rowi = (int*)(smc + OFF_ROWI);
    float* reds = (float*)(smc + OFF_REDS);
    float* redq = (float*)(smc + OFF_REDQ);
    float* dots = (float*)(smc + OFF_DOTS);

    if (tid < 128) {
        par[tid]       = b1[c * H + tid];
        par[128 + tid] = g1[c * H + tid];
        par[256 + tid] = be1[c * H + tid];
        par[384 + tid] = b2[c * H + tid];
        par[512 + tid] = g2[c * H + tid];
        par[640 + tid] = be2[c * H + tid];
        par[768 + tid] = W3[c * H + tid];
        int rr = (tid < m) ? tid : 0;
        int i  = d_perm6[c][m0 + rr];
        rowi[tid] = i;
        offs[tid]       = ei[i] * H;
        offs[128 + tid] = ei[E + i] * H;
        offs[256 + tid] = i * H;
    }
    __syncthreads();

    const int wid   = tid >> 5;
    const int lane  = tid & 31;
    const int gr    = lane >> 2;
    const int tc    = lane & 3;
    const int slab  = (wid & 3) * 32;
    const int nhalf = wid >> 2;
    const int rA0 = slab + gr, rB0 = rA0 + 8, rA1 = rA0 + 16, rB1 = rA0 + 24;

    // ldmatrix lane base addresses (16-row a-frag tiles), buffer-relative
    const uint32_t sb   = smem_u32(smc);
    const int      lrow = lane & 15;
    const int      lcol = lane >> 4;
    const uint32_t aBase = sb + (uint32_t)(slab + lrow) * HROW + lcol * 16;

    // x staging lane mapping (cp.async, 2 rows per warp per it)
    const int rr = wid * 2 + (lane >> 4);
    const int cb = (lane & 15) * 16;   // byte col within 256B row

    float acc[2][8][4];
#pragma unroll
    for (int mf = 0; mf < 2; mf++)
#pragma unroll
        for (int jt = 0; jt < 8; jt++)
#pragma unroll
            for (int u = 0; u < 4; u++) acc[mf][jt][u] = 0.f;

    // B pointer: [c][ks][nt2][lane] uint4; warp reads nt2 = nhalf*4 + jp
    const uint4* wbc = d_wb4 + (((size_t)c * 32) * 8 + nhalf * 4) * 32 + lane;

    // ---- prologue: cp.async seg0 x -> BUF0 ----
#pragma unroll
    for (int it = 0; it < 8; it++) {
        int r = it * 16 + rr;
        const char* src = (const char*)(d_x16 + offs[r]) + cb;
        CP_ASYNC16(sb + BUF0 + (uint32_t)r * HROW + cb, src);
    }
    CP_COMMIT();

    // ================= Layer 1 seg 0: xs, BUF0, B ksteps 0..7 ==================
    CP_WAIT0();
    __syncthreads();
    // prefetch seg1 x -> BUF1 (fully async, no regs held)
#pragma unroll
    for (int it = 0; it < 8; it++) {
        int r = it * 16 + rr;
        const char* src = (const char*)(d_x16 + offs[128 + r]) + cb;
        CP_ASYNC16(sb + BUF1 + (uint32_t)r * HROW + cb, src);
    }
    CP_COMMIT();
    {
        const uint32_t aH0 = aBase + BUF0;
        const uint32_t aH1 = aH0 + 16 * HROW;
#pragma unroll 2
        for (int ks8 = 0; ks8 < 8; ks8++) {
            const uint4* bp = wbc + (size_t)ks8 * 256;
            uint4 bb[4];                       // batched B loads: MLP=4 on L2 miss
            bb[0] = bp[0]; bb[1] = bp[32]; bb[2] = bp[64]; bb[3] = bp[96];
            uint32_t ah0[4], ah1[4];
            ldsm4(ah0, aH0 + ks8 * 32);
            ldsm4(ah1, aH1 + ks8 * 32);
#pragma unroll
            for (int jp = 0; jp < 4; jp++) {
                mma16816(acc[0][jp * 2],     ah0, bb[jp].x, bb[jp].y);
                mma16816(acc[1][jp * 2],     ah1, bb[jp].x, bb[jp].y);
                mma16816(acc[0][jp * 2 + 1], ah0, bb[jp].z, bb[jp].w);
                mma16816(acc[1][jp * 2 + 1], ah1, bb[jp].z, bb[jp].w);
            }
        }
    }

    // ================= Layer 1 seg 1: xe, BUF1, B ksteps 8..15; e -> BUF0 ======
    CP_WAIT0();
    __syncthreads();
    {
        const uint32_t aH0 = aBase + BUF1;
        const uint32_t aH1 = aH0 + 16 * HROW;
        float4 ev[2];
        int    er[2];
#pragma unroll 1
        for (int ks8 = 0; ks8 < 8; ks8++) {
            const uint4* bp = wbc + (size_t)(8 + ks8) * 256;
            uint4 bb[4];
            bb[0] = bp[0]; bb[1] = bp[32]; bb[2] = bp[64]; bb[3] = bp[96];
            // store e batch (loaded one kstep earlier), prefetch next batch
            if (ks8 > 0) {
#pragma unroll
                for (int u = 0; u < 2; u++) {
                    uint32_t h0 = h2bits(__floats2half2_rn(ev[u].x, ev[u].y));
                    uint32_t h1 = h2bits(__floats2half2_rn(ev[u].z, ev[u].w));
                    *(uint2*)(smc + BUF0 + er[u] * HROW + lane * 8) =
                        make_uint2(h0, h1);
                }
            }
#pragma unroll
            for (int u = 0; u < 2; u++) {
                int r = (ks8 * 2 + u) * 8 + wid;
                er[u] = r;
                ev[u] = ldcg4(e + offs[256 + r] + lane * 4);
            }
            uint32_t ah0[4], ah1[4];
            ldsm4(ah0, aH0 + ks8 * 32);
            ldsm4(ah1, aH1 + ks8 * 32);
#pragma unroll
            for (int jp = 0; jp < 4; jp++) {
                mma16816(acc[0][jp * 2],     ah0, bb[jp].x, bb[jp].y);
                mma16816(acc[1][jp * 2],     ah1, bb[jp].x, bb[jp].y);
                mma16816(acc[0][jp * 2 + 1], ah0, bb[jp].z, bb[jp].w);
                mma16816(acc[1][jp * 2 + 1], ah1, bb[jp].z, bb[jp].w);
            }
        }
        // flush last e batch
#pragma unroll
        for (int u = 0; u < 2; u++) {
            uint32_t h0 = h2bits(__floats2half2_rn(ev[u].x, ev[u].y));
            uint32_t h1 = h2bits(__floats2half2_rn(ev[u].z, ev[u].w));
            *(uint2*)(smc + BUF0 + er[u] * HROW + lane * 8) = make_uint2(h0, h1);
        }
    }

    // ================= Layer 1 seg 2: e, BUF0, B ksteps 16..23 =================
    __syncthreads();   // e stores visible; BUF1 reads done
    {
        const uint32_t aH0 = aBase + BUF0;
        const uint32_t aH1 = aH0 + 16 * HROW;
#pragma unroll 2
        for (int ks8 = 0; ks8 < 8; ks8++) {
            const uint4* bp = wbc + (size_t)(16 + ks8) * 256;
            uint4 bb[4];
            bb[0] = bp[0]; bb[1] = bp[32]; bb[2] = bp[64]; bb[3] = bp[96];
            uint32_t ah0[4], ah1[4];
            ldsm4(ah0, aH0 + ks8 * 32);
            ldsm4(ah1, aH1 + ks8 * 32);
#pragma unroll
            for (int jp = 0; jp < 4; jp++) {
                mma16816(acc[0][jp * 2],     ah0, bb[jp].x, bb[jp].y);
                mma16816(acc[1][jp * 2],     ah1, bb[jp].x, bb[jp].y);
                mma16816(acc[0][jp * 2 + 1], ah0, bb[jp].z, bb[jp].w);
                mma16816(acc[1][jp * 2 + 1], ah1, bb[jp].z, bb[jp].w);
            }
        }
    }

    // ---------------- epilogue 1: bias + LN + ReLU -> h in BUF1 ----------------
    __syncthreads();
    {
        float sA[2] = {0, 0}, qA[2] = {0, 0}, sB[2] = {0, 0}, qB[2] = {0, 0};
#pragma unroll
        for (int mf = 0; mf < 2; mf++)
#pragma unroll
            for (int jt = 0; jt < 8; jt++) {
                int col = nhalf * 64 + jt * 8 + tc * 2;
                float2 bb = *(const float2*)(par + col);
                float v0 = acc[mf][jt][0] + bb.x, v1 = acc[mf][jt][1] + bb.y;
                float v2 = acc[mf][jt][2] + bb.x, v3 = acc[mf][jt][3] + bb.y;
                acc[mf][jt][0] = v0; acc[mf][jt][1] = v1;
                acc[mf][jt][2] = v2; acc[mf][jt][3] = v3;
                sA[mf] += v0 + v1; qA[mf] += v0 * v0 + v1 * v1;
                sB[mf] += v2 + v3; qB[mf] += v2 * v2 + v3 * v3;
            }
#pragma unroll
        for (int d = 1; d < 4; d <<= 1) {
            sA[0] += __shfl_xor_sync(~0u, sA[0], d); qA[0] += __shfl_xor_sync(~0u, qA[0], d);
            sB[0] += __shfl_xor_sync(~0u, sB[0], d); qB[0] += __shfl_xor_sync(~0u, qB[0], d);
            sA[1] += __shfl_xor_sync(~0u, sA[1], d); qA[1] += __shfl_xor_sync(~0u, qA[1], d);
            sB[1] += __shfl_xor_sync(~0u, sB[1], d); qB[1] += __shfl_xor_sync(~0u, qB[1], d);
        }
        if (tc == 0) {
            reds[rA0 * 2 + nhalf] = sA[0]; redq[rA0 * 2 + nhalf] = qA[0];
            reds[rB0 * 2 + nhalf] = sB[0]; redq[rB0 * 2 + nhalf] = qB[0];
            reds[rA1 * 2 + nhalf] = sA[1]; redq[rA1 * 2 + nhalf] = qA[1];
            reds[rB1 * 2 + nhalf] = sB[1]; redq[rB1 * 2 + nhalf] = qB[1];
        }
        __syncthreads();
        int   rw[4] = {rA0, rB0, rA1, rB1};
        float mu[4], iv[4];
#pragma unroll
        for (int u = 0; u < 4; u++) {
            float st = reds[rw[u] * 2] + reds[rw[u] * 2 + 1];
            float qt = redq[rw[u] * 2] + redq[rw[u] * 2 + 1];
            mu[u] = st * (1.f / 128.f);
            iv[u] = rsqrtf(qt * (1.f / 128.f) - mu[u] * mu[u] + 1e-5f);
        }
#pragma unroll
        for (int mf = 0; mf < 2; mf++)
#pragma unroll
            for (int jt = 0; jt < 8; jt++) {
                int col = nhalf * 64 + jt * 8 + tc * 2;
                float2 gg = *(const float2*)(par + 128 + col);
                float2 ee = *(const float2*)(par + 256 + col);
                int ua = mf * 2, ub = mf * 2 + 1;
                float h0 = fmaxf((acc[mf][jt][0] - mu[ua]) * iv[ua] * gg.x + ee.x, 0.f);
                float h1 = fmaxf((acc[mf][jt][1] - mu[ua]) * iv[ua] * gg.y + ee.y, 0.f);
                float h2 = fmaxf((acc[mf][jt][2] - mu[ub]) * iv[ub] * gg.x + ee.x, 0.f);
                float h3 = fmaxf((acc[mf][jt][3] - mu[ub]) * iv[ub] * gg.y + ee.y, 0.f);
                *(uint32_t*)(smc + BUF1 + rw[ua] * HROW + col * 2) =
                    h2bits(__floats2half2_rn(h0, h1));
                *(uint32_t*)(smc + BUF1 + rw[ub] * HROW + col * 2) =
                    h2bits(__floats2half2_rn(h2, h3));
            }
    }
    __syncthreads();

    // ================= Layer 2: K = 128, A = h in BUF1 =========================
#pragma unroll
    for (int mf = 0; mf < 2; mf++)
#pragma unroll
        for (int jt = 0; jt < 8; jt++)
#pragma unroll
            for (int u = 0; u < 4; u++) acc[mf][jt][u] = 0.f;

    {
        const uint32_t aH0 = aBase + BUF1;
        const uint32_t aH1 = aH0 + 16 * HROW;
#pragma unroll 2
        for (int ks8 = 0; ks8 < 8; ks8++) {
            const uint4* bp = wbc + (size_t)(24 + ks8) * 256;
            uint4 bb[4];
            bb[0] = bp[0]; bb[1] = bp[32]; bb[2] = bp[64]; bb[3] = bp[96];
            uint32_t ah0[4], ah1[4];
            ldsm4(ah0, aH0 + ks8 * 32);
            ldsm4(ah1, aH1 + ks8 * 32);
#pragma unroll
            for (int jp = 0; jp < 4; jp++) {
                mma16816(acc[0][jp * 2],     ah0, bb[jp].x, bb[jp].y);
                mma16816(acc[1][jp * 2],     ah1, bb[jp].x, bb[jp].y);
                mma16816(acc[0][jp * 2 + 1], ah0, bb[jp].z, bb[jp].w);
                mma16816(acc[1][jp * 2 + 1], ah1, bb[jp].z, bb[jp].w);
            }
        }
    }

    // ---------------- epilogue 2: bias + LN + ReLU + layer-3 dot ---------------
    {
        float sA[2] = {0, 0}, qA[2] = {0, 0}, sB[2] = {0, 0}, qB[2] = {0, 0};
#pragma unroll
        for (int mf = 0; mf < 2; mf++)
#pragma unroll
            for (int jt = 0; jt < 8; jt++) {
                int col = nhalf * 64 + jt * 8 + tc * 2;
                float2 bb = *(const float2*)(par + 384 + col);
                float v0 = acc[mf][jt][0] + bb.x, v1 = acc[mf][jt][1] + bb.y;
                float v2 = acc[mf][jt][2] + bb.x, v3 = acc[mf][jt][3] + bb.y;
                acc[mf][jt][0] = v0; acc[mf][jt][1] = v1;
                acc[mf][jt][2] = v2; acc[mf][jt][3] = v3;
                sA[mf] += v0 + v1; qA[mf] += v0 * v0 + v1 * v1;
                sB[mf] += v2 + v3; qB[mf] += v2 * v2 + v3 * v3;
            }
#pragma unroll
        for (int d = 1; d < 4; d <<= 1) {
            sA[0] += __shfl_xor_sync(~0u, sA[0], d); qA[0] += __shfl_xor_sync(~0u, qA[0], d);
            sB[0] += __shfl_xor_sync(~0u, sB[0], d); qB[0] += __shfl_xor_sync(~0u, qB[0], d);
            sA[1] += __shfl_xor_sync(~0u, sA[1], d); qA[1] += __shfl_xor_sync(~0u, qA[1], d);
            sB[1] += __shfl_xor_sync(~0u, sB[1], d); qB[1] += __shfl_xor_sync(~0u, qB[1], d);
        }
        __syncthreads();   // protect reds/redq reuse
        if (tc == 0) {
            reds[rA0 * 2 + nhalf] = sA[0]; redq[rA0 * 2 + nhalf] = qA[0];
            reds[rB0 * 2 + nhalf] = sB[0]; redq[rB0 * 2 + nhalf] = qB[0];
            reds[rA1 * 2 + nhalf] = sA[1]; redq[rA1 * 2 + nhalf] = qA[1];
            reds[rB1 * 2 + nhalf] = sB[1]; redq[rB1 * 2 + nhalf] = qB[1];
        }
        __syncthreads();
        int   rw[4] = {rA0, rB0, rA1, rB1};
        float mu[4], iv[4], dt[4] = {0, 0, 0, 0};
#pragma unroll
        for (int u = 0; u < 4; u++) {
            float st = reds[rw[u] * 2] + reds[rw[u] * 2 + 1];
            float qt = redq[rw[u] * 2] + redq[rw[u] * 2 + 1];
            mu[u] = st * (1.f / 128.f);
            iv[u] = rsqrtf(qt * (1.f / 128.f) - mu[u] * mu[u] + 1e-5f);
        }
#pragma unroll
        for (int mf = 0; mf < 2; mf++)
#pragma unroll
            for (int jt = 0; jt < 8; jt++) {
                int col = nhalf * 64 + jt * 8 + tc * 2;
                float2 gg = *(const float2*)(par + 512 + col);
                float2 ee = *(const float2*)(par + 640 + col);
                float2 ww = *(const float2*)(par + 768 + col);
                int ua = mf * 2, ub = mf * 2 + 1;
                float h0 = fmaxf((acc[mf][jt][0] - mu[ua]) * iv[ua] * gg.x + ee.x, 0.f);
                float h1 = fmaxf((acc[mf][jt][1] - mu[ua]) * iv[ua] * gg.y + ee.y, 0.f);
                float h2 = fmaxf((acc[mf][jt][2] - mu[ub]) * iv[ub] * gg.x + ee.x, 0.f);
                float h3 = fmaxf((acc[mf][jt][3] - mu[ub]) * iv[ub] * gg.y + ee.y, 0.f);
                dt[ua] += h0 * ww.x + h1 * ww.y;
                dt[ub] += h2 * ww.x + h3 * ww.y;
            }
#pragma unroll
        for (int d = 1; d < 4; d <<= 1) {
            dt[0] += __shfl_xor_sync(~0u, dt[0], d);
            dt[1] += __shfl_xor_sync(~0u, dt[1], d);
            dt[2] += __shfl_xor_sync(~0u, dt[2], d);
            dt[3] += __shfl_xor_sync(~0u, dt[3], d);
        }
        if (tc == 0) {
#pragma unroll
            for (int u = 0; u < 4; u++) dots[rw[u] * 2 + nhalf] = dt[u];
        }
        __syncthreads();
        if (tid < m)
            out[rowi[tid]] = dots[tid * 2] + dots[tid * 2 + 1] + b3[c];
    }
}

// ---------------- launch ----------------------------------------------------------
extern "C" void kernel_launch(void* const* d_in, const int* in_sizes, int n_in,
                              void* d_out, int out_size) {
    const float* x   = (const float*)d_in[0];
    const int*   ei  = (const int*)d_in[1];
    const float* e   = (const float*)d_in[2];
    const int*   vol = (const int*)d_in[3];
    const float* W1  = (const float*)d_in[4];
    const float* b1  = (const float*)d_in[5];
    const float* g1  = (const float*)d_in[6];
    const float* be1 = (const float*)d_in[7];
    const float* W2  = (const float*)d_in[8];
    const float* b2  = (const float*)d_in[9];
    const float* g2  = (const float*)d_in[10];
    const float* be2 = (const float*)d_in[11];
    const float* W3  = (const float*)d_in[12];
    const float* b3  = (const float*)d_in[13];
    float* out = (float*)d_out;

    int E = in_sizes[1] / 2;
    if (E > MAXE) E = MAXE;
    int N = in_sizes[0] / H;
    if (N > MAXN) N = MAXN;

    cudaFuncSetAttribute(k_decode, cudaFuncAttributeMaxDynamicSharedMemorySize, SMEM_BYTES);

    // capture-forked side streams for independent prep work (created once;
    // host-side resources only — no device allocations)
    static cudaStream_t s1 = nullptr, s2 = nullptr;
    static cudaEvent_t  evFork = nullptr, evJ1 = nullptr, evJ2 = nullptr;
    if (!s1) {
        cudaStreamCreateWithFlags(&s1, cudaStreamNonBlocking);
        cudaStreamCreateWithFlags(&s2, cudaStreamNonBlocking);
        cudaEventCreateWithFlags(&evFork, cudaEventDisableTiming);
        cudaEventCreateWithFlags(&evJ1, cudaEventDisableTiming);
        cudaEventCreateWithFlags(&evJ2, cudaEventDisableTiming);
    }

    // fork
    cudaEventRecord(evFork, 0);
    cudaStreamWaitEvent(s1, evFork, 0);
    cudaStreamWaitEvent(s2, evFork, 0);

    // s1: x fp16 convert   s2: weight transform   s0: bucketing (fused prefix)
    int n4 = N * (H / 4);
    k_splitx<<<(n4 + 255) / 256, 256, 0, s1>>>(x, n4);
    k_transW<<<(6 * 32 * 8 * 32 + 255) / 256, 256, 0, s2>>>(W1, W2);
    int nth = (E + 3) / 4;
    k_bucket<<<(nth + 255) / 256, 256>>>(ei, vol, out, E);

    // join
    cudaEventRecord(evJ1, s1);
    cudaEventRecord(evJ2, s2);
    cudaStreamWaitEvent(0, evJ1, 0);
    cudaStreamWaitEvent(0, evJ2, 0);

    int gx = (E + 127) / 128 + 6;
    k_decode<<<gx, 256, SMEM_BYTES>>>(e, ei, b1, g1, be1, b2, g2, be2,
                                      W3, b3, out, E);
}